// round 2
// baseline (speedup 1.0000x reference)
#include <cuda_runtime.h>
#include <math.h>

#define Bd 128
#define Td 512
#define Ed 768
#define Hd 256
#define H4 1024
#define Ld 9

// ---------------- device scratch (static, allowed) ----------------
// xw[dir][t][b][4H]  : input GEMM output with bias folded (536 MB)
__device__ float g_xw[2][Td][Bd][H4];
// h[dir][slot][b][H] : fwd h(t) at slot t+1 (slot 0 = zeros); bwd h(t) at slot t (slot Td = zeros)
__device__ float g_h[2][Td + 1][Bd][Hd];
// software barriers: 8 groups = 2 dirs x 4 batch tiles, 16 CTAs each
__device__ unsigned g_bar_count[8];
__device__ unsigned g_bar_gen[8];

// ---------------- init ----------------
__global__ void init_kernel(float* out) {
    int idx = blockIdx.x * blockDim.x + threadIdx.x;
    const int n = Bd * Hd;
    if (idx < n) {
        ((float*)g_h[0][0])[idx] = 0.f;
        ((float*)g_h[1][Td])[idx] = 0.f;
    }
    if (idx < 8) {
        g_bar_count[idx] = 0u;
        g_bar_gen[idx] = 0u;
    }
    if (idx == 0) out[0] = 0.f;
}

// ---------------- input GEMM: xw = X @ Wih^T + (bih+bhh) ----------------
// M = B*T = 65536, N = 4H = 1024, K = E = 768. Classic 128x128x8 SGEMM.
__global__ void gemm_xw(const float* __restrict__ X,
                        const float* __restrict__ Wf, const float* __restrict__ Wb,
                        const float* __restrict__ bihf, const float* __restrict__ bhhf,
                        const float* __restrict__ bihb, const float* __restrict__ bhhb) {
    __shared__ float As[8][128];
    __shared__ float Bs[8][128];

    const int dir = blockIdx.z;
    const float* W   = dir ? Wb   : Wf;
    const float* bih = dir ? bihb : bihf;
    const float* bhh = dir ? bhhb : bhhf;

    const int m0 = blockIdx.y * 128;
    const int n0 = blockIdx.x * 128;
    const int tid = threadIdx.x;
    const int lrow = tid >> 1;
    const int lcol = (tid & 1) * 4;
    const int ty = tid >> 4;   // 0..15
    const int tx = tid & 15;   // 0..15

    float acc[8][8];
#pragma unroll
    for (int i = 0; i < 8; i++)
#pragma unroll
        for (int j = 0; j < 8; j++) acc[i][j] = 0.f;

    const float* Ap = X + (size_t)(m0 + lrow) * Ed + lcol;
    const float* Bp = W + (size_t)(n0 + lrow) * Ed + lcol;

    for (int k0 = 0; k0 < Ed; k0 += 8) {
        float4 av = *(const float4*)(Ap + k0);
        float4 bv = *(const float4*)(Bp + k0);
        As[lcol + 0][lrow] = av.x; As[lcol + 1][lrow] = av.y;
        As[lcol + 2][lrow] = av.z; As[lcol + 3][lrow] = av.w;
        Bs[lcol + 0][lrow] = bv.x; Bs[lcol + 1][lrow] = bv.y;
        Bs[lcol + 2][lrow] = bv.z; Bs[lcol + 3][lrow] = bv.w;
        __syncthreads();
#pragma unroll
        for (int kk = 0; kk < 8; kk++) {
            float a[8], bb[8];
            *(float4*)&a[0]  = *(const float4*)&As[kk][ty * 8];
            *(float4*)&a[4]  = *(const float4*)&As[kk][ty * 8 + 4];
            *(float4*)&bb[0] = *(const float4*)&Bs[kk][tx * 8];
            *(float4*)&bb[4] = *(const float4*)&Bs[kk][tx * 8 + 4];
#pragma unroll
            for (int i = 0; i < 8; i++)
#pragma unroll
                for (int j = 0; j < 8; j++) acc[i][j] += a[i] * bb[j];
        }
        __syncthreads();
    }

    const int nbase = n0 + tx * 8;
    float bias[8];
#pragma unroll
    for (int j = 0; j < 8; j++) bias[j] = bih[nbase + j] + bhh[nbase + j];

#pragma unroll
    for (int i = 0; i < 8; i++) {
        int m = m0 + ty * 8 + i;
        int b = m >> 9;      // T = 512
        int t = m & 511;
        float* dst = &g_xw[dir][t][b][nbase];
        float4 v0 = make_float4(acc[i][0] + bias[0], acc[i][1] + bias[1],
                                acc[i][2] + bias[2], acc[i][3] + bias[3]);
        float4 v1 = make_float4(acc[i][4] + bias[4], acc[i][5] + bias[5],
                                acc[i][6] + bias[6], acc[i][7] + bias[7]);
        *(float4*)&dst[0] = v0;
        *(float4*)&dst[4] = v1;
    }
}

// ---------------- persistent LSTM recurrence ----------------
// 128 CTAs: dir = blk>>6; within dir: 4 batch tiles (32 b) x 16 H-slices (16 j).
// Per CTA: Whh chunk (64 rows x 256) in smem, c-state in smem, h exchanged via g_h.
#define REC_SMEM_FLOATS (64 * 260 + 32 * 260 + 512)

__device__ __forceinline__ float sigmoidf_fast(float x) {
    return 1.f / (1.f + __expf(-x));
}

__global__ void lstm_rec(const float* __restrict__ Whhf, const float* __restrict__ Whhb) {
    extern __shared__ float sm[];
    float* Ws = sm;                  // [64][260] rows ordered g*16+jj
    float* hs = sm + 64 * 260;       // [32][260]
    float* cs = hs + 32 * 260;       // [16][32]  (jj, b_l)

    const int tid = threadIdx.x;
    const int dir = blockIdx.x >> 6;
    const int c   = blockIdx.x & 63;
    const int bt  = c >> 4;          // 0..3
    const int b0  = bt * 32;
    const int j0  = (c & 15) * 16;
    const int grp = (dir << 2) | bt; // barrier group (16 CTAs)

    const float* Whh = dir ? Whhb : Whhf;

    // load Whh chunk (row-padded to 260 floats to kill LDS bank conflicts)
    for (int idx = tid; idx < 64 * 64; idx += 256) {
        int r  = idx >> 6;            // 0..63
        int k4 = (idx & 63) * 4;
        int g  = r >> 4, jj = r & 15;
        float4 v = *(const float4*)&Whh[(size_t)(g * Hd + j0 + jj) * Hd + k4];
        *(float4*)&Ws[r * 260 + k4] = v;
    }
    for (int idx = tid; idx < 512; idx += 256) cs[idx] = 0.f;

    const int b_l = tid >> 3;   // 0..31
    const int jj  = tid & 7;    // handles jj and jj+8
    __syncthreads();

    for (int s = 0; s < Td; s++) {
        const int t     = dir ? (Td - 1 - s) : s;
        const int rslot = dir ? (t + 1) : t;
        const int wslot = dir ? t : (t + 1);

        // load previous h tile [32 b][256 k] (L2-only loads: written by peer CTAs)
        const float* hsrc = &g_h[dir][rslot][b0][0];
        for (int idx = tid; idx < 32 * 64; idx += 256) {
            int bb = idx >> 6;
            int k4 = (idx & 63) * 4;
            float4 v = __ldcg((const float4*)(hsrc + bb * Hd + k4));
            *(float4*)&hs[bb * 260 + k4] = v;
        }
        __syncthreads();

        // z = xw + h @ Whh_chunk^T  (2 cells per thread: (b_l, jj), (b_l, jj+8))
        const float* xw = &g_xw[dir][t][b0 + b_l][0];
        float acc0[4], acc1[4];
#pragma unroll
        for (int g = 0; g < 4; g++) {
            acc0[g] = xw[g * Hd + j0 + jj];
            acc1[g] = xw[g * Hd + j0 + jj + 8];
        }
        const float* hp = &hs[b_l * 260];
#pragma unroll 8
        for (int k = 0; k < Hd; k += 4) {
            float4 hv = *(const float4*)(hp + k);
#pragma unroll
            for (int g = 0; g < 4; g++) {
                float4 w0 = *(const float4*)&Ws[(g * 16 + jj) * 260 + k];
                float4 w1 = *(const float4*)&Ws[(g * 16 + jj + 8) * 260 + k];
                acc0[g] += hv.x * w0.x + hv.y * w0.y + hv.z * w0.z + hv.w * w0.w;
                acc1[g] += hv.x * w1.x + hv.y * w1.y + hv.z * w1.z + hv.w * w1.w;
            }
        }

        // gates (PyTorch order i,f,g,o)
        float c0 = cs[jj * 32 + b_l];
        float c1 = cs[(jj + 8) * 32 + b_l];
        float i0 = sigmoidf_fast(acc0[0]);
        float f0 = sigmoidf_fast(acc0[1]);
        float g0 = tanhf(acc0[2]);
        float o0 = sigmoidf_fast(acc0[3]);
        c0 = f0 * c0 + i0 * g0;
        float h0 = o0 * tanhf(c0);
        float i1 = sigmoidf_fast(acc1[0]);
        float f1 = sigmoidf_fast(acc1[1]);
        float g1 = tanhf(acc1[2]);
        float o1 = sigmoidf_fast(acc1[3]);
        c1 = f1 * c1 + i1 * g1;
        float h1 = o1 * tanhf(c1);
        cs[jj * 32 + b_l] = c0;
        cs[(jj + 8) * 32 + b_l] = c1;

        float* hdst = &g_h[dir][wslot][b0 + b_l][j0];
        hdst[jj]     = h0;
        hdst[jj + 8] = h1;

        // group barrier (16 CTAs sharing this batch tile + dir)
        __threadfence();
        __syncthreads();
        if (tid == 0) {
            unsigned arr = atomicAdd(&g_bar_count[grp], 1u);
            if (arr == 15u) {
                g_bar_count[grp] = 0u;
                __threadfence();
                atomicAdd(&g_bar_gen[grp], 1u);
            } else {
                while (*((volatile unsigned*)&g_bar_gen[grp]) < (unsigned)(s + 1))
                    __nanosleep(64);
                __threadfence();
            }
        }
        __syncthreads();
    }
}

// ---------------- emissions + CRF NLL (one CTA per batch) ----------------
// labels may arrive as int32 or int64 depending on harness dtype handling.
// Detect: values are in [0,9), so under int64 every odd int32 word of the
// first 128 words is zero; under int32 that has probability ~(1/9)^63 ~ 0.
__global__ void emis_crf(const int* __restrict__ mask, const int* __restrict__ labels32,
                         const float* __restrict__ Wout, const float* __restrict__ bout,
                         const float* __restrict__ start_t, const float* __restrict__ end_t,
                         const float* __restrict__ trans, float* out) {
    __shared__ float Wsm[Ld * 2 * Hd];   // 9 x 512
    __shared__ float em[Td * Ld];        // 512 x 9
    __shared__ float tr[Ld * Ld];
    __shared__ int msk[Td];
    __shared__ int lab[Td];
    __shared__ int lab_is64;
    __shared__ float score_sm;
    __shared__ float logZ_sm;

    const int b = blockIdx.x;
    const int tid = threadIdx.x;

    if (tid == 0) {
        int odd_or = 0;
        for (int i = 1; i < 128; i += 2) odd_or |= labels32[i];
        lab_is64 = (odd_or == 0) ? 1 : 0;
    }
    for (int i = tid; i < Ld * 2 * Hd; i += blockDim.x) Wsm[i] = Wout[i];
    for (int i = tid; i < Td; i += blockDim.x) msk[i] = mask[(size_t)b * Td + i];
    for (int i = tid; i < Ld * Ld; i += blockDim.x) tr[i] = trans[i];
    __syncthreads();
    const int stride = lab_is64 ? 2 : 1;
    for (int i = tid; i < Td; i += blockDim.x)
        lab[i] = labels32[((size_t)b * Td + i) * stride];
    __syncthreads();

    // emissions: warp w handles t = w, w+8, ...
    const int w = tid >> 5, lane = tid & 31;
    for (int t = w; t < Td; t += 8) {
        float p[Ld];
#pragma unroll
        for (int l = 0; l < Ld; l++) p[l] = 0.f;
        const float* hf = &g_h[0][t + 1][b][0];
        const float* hb = &g_h[1][t][b][0];
#pragma unroll
        for (int kk = 0; kk < 8; kk++) {
            int k = kk * 32 + lane;
            float hv = hf[k];
#pragma unroll
            for (int l = 0; l < Ld; l++) p[l] += hv * Wsm[l * 512 + k];
        }
#pragma unroll
        for (int kk = 0; kk < 8; kk++) {
            int k = kk * 32 + lane;
            float hv = hb[k];
#pragma unroll
            for (int l = 0; l < Ld; l++) p[l] += hv * Wsm[l * 512 + 256 + k];
        }
#pragma unroll
        for (int l = 0; l < Ld; l++) {
            float v = p[l];
#pragma unroll
            for (int off = 16; off; off >>= 1) v += __shfl_down_sync(0xffffffffu, v, off);
            if (lane == 0) em[t * Ld + l] = v + bout[l];
        }
    }
    __syncthreads();

    // gold path score (single thread; mask is a contiguous prefix)
    if (tid == 32) {
        int prev = lab[0];
        float sc = start_t[prev] + em[0 * Ld + prev];
        for (int t = 1; t < Td; t++) {
            if (msk[t]) {
                int cur = lab[t];
                sc += em[t * Ld + cur] + tr[prev * Ld + cur];
                prev = cur;
            }
        }
        sc += end_t[prev];
        score_sm = sc;
    }

    // forward algorithm on warp 0 (lane j holds alpha[j])
    if (tid < 32) {
        const int j = lane;
        const bool act = j < Ld;
        float tcol[Ld];
#pragma unroll
        for (int i = 0; i < Ld; i++) tcol[i] = act ? tr[i * Ld + j] : 0.f;
        float alpha = act ? (start_t[j] + em[0 * Ld + j]) : -1e30f;
        for (int t = 1; t < Td; t++) {
            float vv[Ld];
            float mx = -1e30f;
#pragma unroll
            for (int i = 0; i < Ld; i++) {
                float ai = __shfl_sync(0xffffffffu, alpha, i);
                vv[i] = ai + tcol[i];
                mx = fmaxf(mx, vv[i]);
            }
            float ssum = 0.f;
#pragma unroll
            for (int i = 0; i < Ld; i++) ssum += __expf(vv[i] - mx);
            float nxt = mx + __logf(ssum) + (act ? em[t * Ld + j] : 0.f);
            if (msk[t]) alpha = nxt;
        }
        float v = act ? (alpha + end_t[j]) : -1e30f;
        float mx = v;
#pragma unroll
        for (int off = 16; off; off >>= 1) mx = fmaxf(mx, __shfl_xor_sync(0xffffffffu, mx, off));
        float s = __expf(v - mx);
#pragma unroll
        for (int off = 16; off; off >>= 1) s += __shfl_xor_sync(0xffffffffu, s, off);
        if (lane == 0) logZ_sm = mx + __logf(s);
    }
    __syncthreads();
    if (tid == 0) atomicAdd(out, logZ_sm - score_sm);
}

// ---------------- launch ----------------
extern "C" void kernel_launch(void* const* d_in, const int* in_sizes, int n_in,
                              void* d_out, int out_size) {
    const float* X      = (const float*)d_in[0];
    const int*   mask   = (const int*)d_in[1];
    const int*   labels = (const int*)d_in[2];   // int32 or int64 (detected on device)
    const float* Wih_f = (const float*)d_in[3];
    const float* Whh_f = (const float*)d_in[4];
    const float* bih_f = (const float*)d_in[5];
    const float* bhh_f = (const float*)d_in[6];
    const float* Wih_b = (const float*)d_in[7];
    const float* Whh_b = (const float*)d_in[8];
    const float* bih_b = (const float*)d_in[9];
    const float* bhh_b = (const float*)d_in[10];
    const float* W_out = (const float*)d_in[11];
    const float* b_out = (const float*)d_in[12];
    const float* start_t = (const float*)d_in[13];
    const float* end_t   = (const float*)d_in[14];
    const float* trans   = (const float*)d_in[15];
    float* out = (float*)d_out;

    const int rec_smem = REC_SMEM_FLOATS * (int)sizeof(float);
    cudaFuncSetAttribute(lstm_rec, cudaFuncAttributeMaxDynamicSharedMemorySize, rec_smem);

    init_kernel<<<128, 256>>>(out);
    gemm_xw<<<dim3(8, 512, 2), 256>>>(X, Wih_f, Wih_b, bih_f, bhh_f, bih_b, bhh_b);
    lstm_rec<<<128, 256, rec_smem>>>(Whh_f, Whh_b);
    emis_crf<<<128, 256>>>(mask, labels, W_out, b_out, start_t, end_t, trans, out);
}

// round 3
// speedup vs baseline: 1.3576x; 1.3576x over previous
#include <cuda_runtime.h>
#include <cuda_bf16.h>
#include <math.h>
#include <stdint.h>

#define Bd 128
#define Td 512
#define Ed 768
#define Hd 256
#define H4 1024
#define Ld 9

// ---------------- device scratch (static, allowed) ----------------
__device__ float g_xw[2][Td][Bd][H4];
__device__ float g_h[2][Td + 1][Bd][Hd];
__device__ unsigned g_bar_count[8];
__device__ unsigned g_bar_gen[8];

// ---------------- init ----------------
__global__ void init_kernel(float* out) {
    int idx = blockIdx.x * blockDim.x + threadIdx.x;
    const int n = Bd * Hd;
    if (idx < n) {
        ((float*)g_h[0][0])[idx] = 0.f;
        ((float*)g_h[1][Td])[idx] = 0.f;
    }
    if (idx < 8) {
        g_bar_count[idx] = 0u;
        g_bar_gen[idx] = 0u;
    }
    if (idx == 0) out[0] = 0.f;
}

// ---------------- tensor-core helpers ----------------
__device__ __forceinline__ void ldsm4(uint32_t (&r)[4], uint32_t addr) {
    asm volatile("ldmatrix.sync.aligned.m8n8.x4.shared.b16 {%0,%1,%2,%3}, [%4];"
                 : "=r"(r[0]), "=r"(r[1]), "=r"(r[2]), "=r"(r[3]) : "r"(addr));
}
__device__ __forceinline__ void mma_bf16(float (&d)[4], const uint32_t (&a)[4],
                                         uint32_t b0, uint32_t b1) {
    asm volatile(
        "mma.sync.aligned.m16n8k16.row.col.f32.bf16.bf16.f32 "
        "{%0,%1,%2,%3}, {%4,%5,%6,%7}, {%8,%9}, {%0,%1,%2,%3};"
        : "+f"(d[0]), "+f"(d[1]), "+f"(d[2]), "+f"(d[3])
        : "r"(a[0]), "r"(a[1]), "r"(a[2]), "r"(a[3]), "r"(b0), "r"(b1));
}
__device__ __forceinline__ void cvt_split_store(float4 v, __nv_bfloat16* hi, __nv_bfloat16* lo) {
    __nv_bfloat16 h0 = __float2bfloat16(v.x);
    __nv_bfloat16 h1 = __float2bfloat16(v.y);
    __nv_bfloat16 h2 = __float2bfloat16(v.z);
    __nv_bfloat16 h3 = __float2bfloat16(v.w);
    __nv_bfloat16 l0 = __float2bfloat16(v.x - __bfloat162float(h0));
    __nv_bfloat16 l1 = __float2bfloat16(v.y - __bfloat162float(h1));
    __nv_bfloat16 l2 = __float2bfloat16(v.z - __bfloat162float(h2));
    __nv_bfloat16 l3 = __float2bfloat16(v.w - __bfloat162float(h3));
    ((__nv_bfloat162*)hi)[0] = __halves2bfloat162(h0, h1);
    ((__nv_bfloat162*)hi)[1] = __halves2bfloat162(h2, h3);
    ((__nv_bfloat162*)lo)[0] = __halves2bfloat162(l0, l1);
    ((__nv_bfloat162*)lo)[1] = __halves2bfloat162(l2, l3);
}

// ---------------- input GEMM (tensor cores, bf16x3 = emulated fp32) ----------------
// xw = X @ Wih^T + (bih+bhh).  M=B*T=65536, N=1024, K=768, 2 dirs.
// CTA tile 128x128x32, 8 warps (4m x 2n), warp tile 32x64.
// smem: per stage, A/B hi+lo bf16 planes, rows padded to 40 bf16 (80B) for
// conflict-free ldmatrix. 2 stages = 81920 B.
#define GSTG 20480           // bf16 elements per stage
#define GPLN 5120            // bf16 elements per plane (128*40)

__global__ void __launch_bounds__(256, 1)
gemm_xw_tc(const float* __restrict__ X,
           const float* __restrict__ Wf, const float* __restrict__ Wb,
           const float* __restrict__ bihf, const float* __restrict__ bhhf,
           const float* __restrict__ bihb, const float* __restrict__ bhhb) {
    extern __shared__ __nv_bfloat16 smbf[];

    const int dir = blockIdx.z;
    const float* __restrict__ W   = dir ? Wb   : Wf;
    const float* __restrict__ bih = dir ? bihb : bihf;
    const float* __restrict__ bhh = dir ? bhhb : bhhf;

    const int m0 = blockIdx.y * 128;
    const int n0 = blockIdx.x * 128;
    const int tid = threadIdx.x;
    const int lane = tid & 31;
    const int warp = tid >> 5;
    const int wm = (warp >> 1) << 5;   // 0,32,64,96
    const int wn = (warp & 1) << 6;    // 0,64

    const uint32_t smem_base = (uint32_t)__cvta_generic_to_shared(smbf);

    // per-thread global-load coords (4 float4 of A + 4 of B per stage)
    int lrow[4], lcol[4];
    const float *Ag[4], *Bg[4];
#pragma unroll
    for (int i = 0; i < 4; i++) {
        int idx = tid + i * 256;
        lrow[i] = idx >> 3;
        lcol[i] = (idx & 7) * 4;
        Ag[i] = X + (size_t)(m0 + lrow[i]) * Ed + lcol[i];
        Bg[i] = W + (size_t)(n0 + lrow[i]) * Ed + lcol[i];
    }

    float4 ra[4], rb[4];

    // prologue: load + convert-store stage 0
#pragma unroll
    for (int i = 0; i < 4; i++) {
        ra[i] = *(const float4*)(Ag[i]);
        rb[i] = *(const float4*)(Bg[i]);
    }
#pragma unroll
    for (int i = 0; i < 4; i++) {
        int off = lrow[i] * 40 + lcol[i];
        cvt_split_store(ra[i], &smbf[off], &smbf[off + GPLN]);
        cvt_split_store(rb[i], &smbf[off + 2 * GPLN], &smbf[off + 3 * GPLN]);
    }
    __syncthreads();

    float acc[2][8][4];
#pragma unroll
    for (int i = 0; i < 2; i++)
#pragma unroll
        for (int j = 0; j < 8; j++)
#pragma unroll
            for (int q = 0; q < 4; q++) acc[i][j][q] = 0.f;

    int stage = 0;
#pragma unroll 1
    for (int k0 = 0; k0 < Ed; k0 += 32) {
        const bool more = (k0 + 32) < Ed;
        if (more) {
#pragma unroll
            for (int i = 0; i < 4; i++) {
                ra[i] = *(const float4*)(Ag[i] + k0 + 32);
                rb[i] = *(const float4*)(Bg[i] + k0 + 32);
            }
        }

        const uint32_t so = stage * GSTG;
#pragma unroll
        for (int ks = 0; ks < 32; ks += 16) {
            uint32_t ah[2][4], al[2][4];
            const int arow = lane & 15;
            const int acol = ks + ((lane >> 4) << 3);
#pragma unroll
            for (int i = 0; i < 2; i++) {
                uint32_t aoff = so + (uint32_t)((wm + i * 16 + arow) * 40 + acol);
                ldsm4(ah[i], smem_base + aoff * 2);
                ldsm4(al[i], smem_base + (aoff + GPLN) * 2);
            }
            const int brow = ((lane >> 4) << 3) + (lane & 7);
            const int bcol = ks + (((lane >> 3) & 1) << 3);
#pragma unroll
            for (int g = 0; g < 4; g++) {
                uint32_t boff = so + 2 * GPLN + (uint32_t)((wn + g * 16 + brow) * 40 + bcol);
                uint32_t bh[4], bl[4];
                ldsm4(bh, smem_base + boff * 2);
                ldsm4(bl, smem_base + (boff + GPLN) * 2);
#pragma unroll
                for (int i = 0; i < 2; i++) {
                    mma_bf16(acc[i][2 * g],     ah[i], bh[0], bh[1]);
                    mma_bf16(acc[i][2 * g],     ah[i], bl[0], bl[1]);
                    mma_bf16(acc[i][2 * g],     al[i], bh[0], bh[1]);
                    mma_bf16(acc[i][2 * g + 1], ah[i], bh[2], bh[3]);
                    mma_bf16(acc[i][2 * g + 1], ah[i], bl[2], bl[3]);
                    mma_bf16(acc[i][2 * g + 1], al[i], bh[2], bh[3]);
                }
            }
        }

        if (more) {
            const int ns = stage ^ 1;
#pragma unroll
            for (int i = 0; i < 4; i++) {
                int off = ns * GSTG + lrow[i] * 40 + lcol[i];
                cvt_split_store(ra[i], &smbf[off], &smbf[off + GPLN]);
                cvt_split_store(rb[i], &smbf[off + 2 * GPLN], &smbf[off + 3 * GPLN]);
            }
            __syncthreads();
            stage = ns;
        }
    }

    // epilogue: add bias, scatter to g_xw[dir][t][b][n]
    const int lr = lane >> 2;
    const int lc = (lane & 3) * 2;
#pragma unroll
    for (int j = 0; j < 8; j++) {
        const int n = n0 + wn + j * 8 + lc;
        const float b0 = bih[n] + bhh[n];
        const float b1 = bih[n + 1] + bhh[n + 1];
#pragma unroll
        for (int i = 0; i < 2; i++) {
            int m = m0 + wm + i * 16 + lr;
            int bb = m >> 9, t = m & 511;
            float2 v0 = make_float2(acc[i][j][0] + b0, acc[i][j][1] + b1);
            *(float2*)&g_xw[dir][t][bb][n] = v0;
            m += 8; bb = m >> 9; t = m & 511;
            float2 v1 = make_float2(acc[i][j][2] + b0, acc[i][j][3] + b1);
            *(float2*)&g_xw[dir][t][bb][n] = v1;
        }
    }
}

// ---------------- persistent LSTM recurrence (unchanged, proven) ----------------
#define REC_SMEM_FLOATS (64 * 260 + 32 * 260 + 512)

__device__ __forceinline__ float sigmoidf_fast(float x) {
    return 1.f / (1.f + __expf(-x));
}

__global__ void lstm_rec(const float* __restrict__ Whhf, const float* __restrict__ Whhb) {
    extern __shared__ float sm[];
    float* Ws = sm;                  // [64][260]
    float* hs = sm + 64 * 260;       // [32][260]
    float* cs = hs + 32 * 260;       // [16][32]

    const int tid = threadIdx.x;
    const int dir = blockIdx.x >> 6;
    const int c   = blockIdx.x & 63;
    const int bt  = c >> 4;
    const int b0  = bt * 32;
    const int j0  = (c & 15) * 16;
    const int grp = (dir << 2) | bt;

    const float* Whh = dir ? Whhb : Whhf;

    for (int idx = tid; idx < 64 * 64; idx += 256) {
        int r  = idx >> 6;
        int k4 = (idx & 63) * 4;
        int g  = r >> 4, jj = r & 15;
        float4 v = *(const float4*)&Whh[(size_t)(g * Hd + j0 + jj) * Hd + k4];
        *(float4*)&Ws[r * 260 + k4] = v;
    }
    for (int idx = tid; idx < 512; idx += 256) cs[idx] = 0.f;

    const int b_l = tid >> 3;
    const int jj  = tid & 7;
    __syncthreads();

    for (int s = 0; s < Td; s++) {
        const int t     = dir ? (Td - 1 - s) : s;
        const int rslot = dir ? (t + 1) : t;
        const int wslot = dir ? t : (t + 1);

        const float* hsrc = &g_h[dir][rslot][b0][0];
        for (int idx = tid; idx < 32 * 64; idx += 256) {
            int bb = idx >> 6;
            int k4 = (idx & 63) * 4;
            float4 v = __ldcg((const float4*)(hsrc + bb * Hd + k4));
            *(float4*)&hs[bb * 260 + k4] = v;
        }
        __syncthreads();

        const float* xw = &g_xw[dir][t][b0 + b_l][0];
        float acc0[4], acc1[4];
#pragma unroll
        for (int g = 0; g < 4; g++) {
            acc0[g] = xw[g * Hd + j0 + jj];
            acc1[g] = xw[g * Hd + j0 + jj + 8];
        }
        const float* hp = &hs[b_l * 260];
#pragma unroll 8
        for (int k = 0; k < Hd; k += 4) {
            float4 hv = *(const float4*)(hp + k);
#pragma unroll
            for (int g = 0; g < 4; g++) {
                float4 w0 = *(const float4*)&Ws[(g * 16 + jj) * 260 + k];
                float4 w1 = *(const float4*)&Ws[(g * 16 + jj + 8) * 260 + k];
                acc0[g] += hv.x * w0.x + hv.y * w0.y + hv.z * w0.z + hv.w * w0.w;
                acc1[g] += hv.x * w1.x + hv.y * w1.y + hv.z * w1.z + hv.w * w1.w;
            }
        }

        float c0 = cs[jj * 32 + b_l];
        float c1 = cs[(jj + 8) * 32 + b_l];
        float i0 = sigmoidf_fast(acc0[0]);
        float f0 = sigmoidf_fast(acc0[1]);
        float g0 = tanhf(acc0[2]);
        float o0 = sigmoidf_fast(acc0[3]);
        c0 = f0 * c0 + i0 * g0;
        float h0 = o0 * tanhf(c0);
        float i1 = sigmoidf_fast(acc1[0]);
        float f1 = sigmoidf_fast(acc1[1]);
        float g1 = tanhf(acc1[2]);
        float o1 = sigmoidf_fast(acc1[3]);
        c1 = f1 * c1 + i1 * g1;
        float h1 = o1 * tanhf(c1);
        cs[jj * 32 + b_l] = c0;
        cs[(jj + 8) * 32 + b_l] = c1;

        float* hdst = &g_h[dir][wslot][b0 + b_l][j0];
        hdst[jj]     = h0;
        hdst[jj + 8] = h1;

        __threadfence();
        __syncthreads();
        if (tid == 0) {
            unsigned arr = atomicAdd(&g_bar_count[grp], 1u);
            if (arr == 15u) {
                g_bar_count[grp] = 0u;
                __threadfence();
                atomicAdd(&g_bar_gen[grp], 1u);
            } else {
                while (*((volatile unsigned*)&g_bar_gen[grp]) < (unsigned)(s + 1))
                    __nanosleep(64);
                __threadfence();
            }
        }
        __syncthreads();
    }
}

// ---------------- emissions + CRF NLL (unchanged, proven) ----------------
__global__ void emis_crf(const int* __restrict__ mask, const int* __restrict__ labels32,
                         const float* __restrict__ Wout, const float* __restrict__ bout,
                         const float* __restrict__ start_t, const float* __restrict__ end_t,
                         const float* __restrict__ trans, float* out) {
    __shared__ float Wsm[Ld * 2 * Hd];
    __shared__ float em[Td * Ld];
    __shared__ float tr[Ld * Ld];
    __shared__ int msk[Td];
    __shared__ int lab[Td];
    __shared__ int lab_is64;
    __shared__ float score_sm;
    __shared__ float logZ_sm;

    const int b = blockIdx.x;
    const int tid = threadIdx.x;

    if (tid == 0) {
        int odd_or = 0;
        for (int i = 1; i < 128; i += 2) odd_or |= labels32[i];
        lab_is64 = (odd_or == 0) ? 1 : 0;
    }
    for (int i = tid; i < Ld * 2 * Hd; i += blockDim.x) Wsm[i] = Wout[i];
    for (int i = tid; i < Td; i += blockDim.x) msk[i] = mask[(size_t)b * Td + i];
    for (int i = tid; i < Ld * Ld; i += blockDim.x) tr[i] = trans[i];
    __syncthreads();
    const int stride = lab_is64 ? 2 : 1;
    for (int i = tid; i < Td; i += blockDim.x)
        lab[i] = labels32[((size_t)b * Td + i) * stride];
    __syncthreads();

    const int w = tid >> 5, lane = tid & 31;
    for (int t = w; t < Td; t += 8) {
        float p[Ld];
#pragma unroll
        for (int l = 0; l < Ld; l++) p[l] = 0.f;
        const float* hf = &g_h[0][t + 1][b][0];
        const float* hb = &g_h[1][t][b][0];
#pragma unroll
        for (int kk = 0; kk < 8; kk++) {
            int k = kk * 32 + lane;
            float hv = hf[k];
#pragma unroll
            for (int l = 0; l < Ld; l++) p[l] += hv * Wsm[l * 512 + k];
        }
#pragma unroll
        for (int kk = 0; kk < 8; kk++) {
            int k = kk * 32 + lane;
            float hv = hb[k];
#pragma unroll
            for (int l = 0; l < Ld; l++) p[l] += hv * Wsm[l * 512 + 256 + k];
        }
#pragma unroll
        for (int l = 0; l < Ld; l++) {
            float v = p[l];
#pragma unroll
            for (int off = 16; off; off >>= 1) v += __shfl_down_sync(0xffffffffu, v, off);
            if (lane == 0) em[t * Ld + l] = v + bout[l];
        }
    }
    __syncthreads();

    if (tid == 32) {
        int prev = lab[0];
        float sc = start_t[prev] + em[0 * Ld + prev];
        for (int t = 1; t < Td; t++) {
            if (msk[t]) {
                int cur = lab[t];
                sc += em[t * Ld + cur] + tr[prev * Ld + cur];
                prev = cur;
            }
        }
        sc += end_t[prev];
        score_sm = sc;
    }

    if (tid < 32) {
        const int j = lane;
        const bool act = j < Ld;
        float tcol[Ld];
#pragma unroll
        for (int i = 0; i < Ld; i++) tcol[i] = act ? tr[i * Ld + j] : 0.f;
        float alpha = act ? (start_t[j] + em[0 * Ld + j]) : -1e30f;
        for (int t = 1; t < Td; t++) {
            float vv[Ld];
            float mx = -1e30f;
#pragma unroll
            for (int i = 0; i < Ld; i++) {
                float ai = __shfl_sync(0xffffffffu, alpha, i);
                vv[i] = ai + tcol[i];
                mx = fmaxf(mx, vv[i]);
            }
            float ssum = 0.f;
#pragma unroll
            for (int i = 0; i < Ld; i++) ssum += __expf(vv[i] - mx);
            float nxt = mx + __logf(ssum) + (act ? em[t * Ld + j] : 0.f);
            if (msk[t]) alpha = nxt;
        }
        float v = act ? (alpha + end_t[j]) : -1e30f;
        float mx = v;
#pragma unroll
        for (int off = 16; off; off >>= 1) mx = fmaxf(mx, __shfl_xor_sync(0xffffffffu, mx, off));
        float s = __expf(v - mx);
#pragma unroll
        for (int off = 16; off; off >>= 1) s += __shfl_xor_sync(0xffffffffu, s, off);
        if (lane == 0) logZ_sm = mx + __logf(s);
    }
    __syncthreads();
    if (tid == 0) atomicAdd(out, logZ_sm - score_sm);
}

// ---------------- launch ----------------
extern "C" void kernel_launch(void* const* d_in, const int* in_sizes, int n_in,
                              void* d_out, int out_size) {
    const float* X      = (const float*)d_in[0];
    const int*   mask   = (const int*)d_in[1];
    const int*   labels = (const int*)d_in[2];
    const float* Wih_f = (const float*)d_in[3];
    const float* Whh_f = (const float*)d_in[4];
    const float* bih_f = (const float*)d_in[5];
    const float* bhh_f = (const float*)d_in[6];
    const float* Wih_b = (const float*)d_in[7];
    const float* Whh_b = (const float*)d_in[8];
    const float* bih_b = (const float*)d_in[9];
    const float* bhh_b = (const float*)d_in[10];
    const float* W_out = (const float*)d_in[11];
    const float* b_out = (const float*)d_in[12];
    const float* start_t = (const float*)d_in[13];
    const float* end_t   = (const float*)d_in[14];
    const float* trans   = (const float*)d_in[15];
    float* out = (float*)d_out;

    const int rec_smem  = REC_SMEM_FLOATS * (int)sizeof(float);
    const int gemm_smem = 2 * GSTG * (int)sizeof(__nv_bfloat16);   // 81920
    cudaFuncSetAttribute(lstm_rec, cudaFuncAttributeMaxDynamicSharedMemorySize, rec_smem);
    cudaFuncSetAttribute(gemm_xw_tc, cudaFuncAttributeMaxDynamicSharedMemorySize, gemm_smem);

    init_kernel<<<128, 256>>>(out);
    gemm_xw_tc<<<dim3(8, 512, 2), 256, gemm_smem>>>(X, Wih_f, Wih_b,
                                                    bih_f, bhh_f, bih_b, bhh_b);
    lstm_rec<<<128, 256, rec_smem>>>(Whh_f, Whh_b);
    emis_crf<<<128, 256>>>(mask, labels, W_out, b_out, start_t, end_t, trans, out);
}